// round 1
// baseline (speedup 1.0000x reference)
#include <cuda_runtime.h>
#include <cuda_fp16.h>
#include <stdint.h>

#define TOKENS 8192
#define DIN    4096
#define DOUT   4096
#define RANK   256

// ---------------- scratch (static device globals: allocation-free) ----------------
__device__ __half g_xh[(size_t)TOKENS * DIN];   // x in fp16
__device__ __half g_qh[(size_t)DOUT * DIN];     // dequantized Q
__device__ __half g_rh[(size_t)RANK * DIN];     // dequantized R
__device__ __half g_lh[(size_t)DOUT * RANK];    // dequantized L
__device__ __half g_xr[(size_t)TOKENS * RANK];  // xr = x @ R^T in fp16

// ---------------- small conversion kernels ----------------
__global__ void cvt_x_kernel(const float* __restrict__ x) {
    int i = blockIdx.x * blockDim.x + threadIdx.x;  // grid sized exactly
    float4 v = reinterpret_cast<const float4*>(x)[i];
    __half2* o = reinterpret_cast<__half2*>(g_xh);
    o[2 * i]     = __floats2half2_rn(v.x, v.y);
    o[2 * i + 1] = __floats2half2_rn(v.z, v.w);
}

// groupwise dequant: out[r][c] = values[r][c] * scales[r][c/128], fp16 result
__global__ void deq_kernel(const int* __restrict__ v, const float* __restrict__ s,
                           __half* __restrict__ o, int cols_log2) {
    int i = blockIdx.x * blockDim.x + threadIdx.x;  // grid sized exactly
    int4 q = reinterpret_cast<const int4*>(v)[i];
    int e = i << 2;
    int r = e >> cols_log2;
    int c = e & ((1 << cols_log2) - 1);
    float sc = s[(r << (cols_log2 - 7)) + (c >> 7)];
    __half2* po = reinterpret_cast<__half2*>(o);
    po[2 * i]     = __floats2half2_rn(q.x * sc, q.y * sc);
    po[2 * i + 1] = __floats2half2_rn(q.z * sc, q.w * sc);
}

// ---------------- GEMM building blocks (mma.sync m16n8k16 f16->f32) ----------------
__device__ __forceinline__ void cp_async16(uint32_t dst, const void* src) {
    asm volatile("cp.async.cg.shared.global [%0], [%1], 16;\n" :: "r"(dst), "l"(src));
}
__device__ __forceinline__ void cp_commit() {
    asm volatile("cp.async.commit_group;\n" ::: "memory");
}
template <int N>
__device__ __forceinline__ void cp_wait() {
    asm volatile("cp.async.wait_group %0;\n" :: "n"(N) : "memory");
}
__device__ __forceinline__ void ldsm4(uint32_t r[4], uint32_t addr) {
    asm volatile("ldmatrix.sync.aligned.m8n8.x4.shared.b16 {%0,%1,%2,%3}, [%4];\n"
                 : "=r"(r[0]), "=r"(r[1]), "=r"(r[2]), "=r"(r[3]) : "r"(addr));
}
__device__ __forceinline__ void mma16816(float c[4], const uint32_t a[4],
                                         uint32_t b0, uint32_t b1) {
    asm volatile("mma.sync.aligned.m16n8k16.row.col.f32.f16.f16.f32 "
                 "{%0,%1,%2,%3},{%4,%5,%6,%7},{%8,%9},{%0,%1,%2,%3};\n"
                 : "+f"(c[0]), "+f"(c[1]), "+f"(c[2]), "+f"(c[3])
                 : "r"(a[0]), "r"(a[1]), "r"(a[2]), "r"(a[3]), "r"(b0), "r"(b1));
}

// Block tile: BM=128, BN=128, BK=64 halves (128B rows). Smem layout per tile:
// addr(row, col) = base + row*128 + (((col>>3) ^ (row&7)) << 4) + (col&7)*2
// 8-chunk XOR swizzle -> conflict-free ldmatrix and cp.async stores.
__device__ __forceinline__ void load_tile(uint32_t sbase, const __half* __restrict__ g,
                                          int ld, int row0, int k0, int tid) {
    #pragma unroll
    for (int j = 0; j < 4; j++) {
        int idx = tid + j * 256;     // 1024 chunks of 16B, 256 threads
        int r = idx >> 3;
        int ch = idx & 7;
        const __half* src = g + (size_t)(row0 + r) * ld + (k0 + ch * 8);
        uint32_t dst = sbase + r * 128 + ((ch ^ (r & 7)) << 4);
        cp_async16(dst, src);
    }
}

// 8 warps as 2(M) x 4(N): warp tile 64x32 -> 4x4 mma tiles per kstep, 4 ksteps.
__device__ __forceinline__ void mma_stage(uint32_t sA, uint32_t sB, int lane,
                                          int wm, int wn, float (&c)[4][4][4]) {
    const int lr = lane & 15;
    const int lc = lane >> 4;
    #pragma unroll
    for (int ks = 0; ks < 4; ks++) {
        uint32_t a[4][4];
        uint32_t b[2][4];
        #pragma unroll
        for (int im = 0; im < 4; im++) {
            int row = wm * 64 + im * 16 + lr;
            int ch = (ks * 2 + lc) ^ (row & 7);
            ldsm4(a[im], sA + row * 128 + (ch << 4));
        }
        #pragma unroll
        for (int j = 0; j < 2; j++) {
            int row = wn * 32 + j * 16 + lr;
            int ch = (ks * 2 + lc) ^ (row & 7);
            ldsm4(b[j], sB + row * 128 + (ch << 4));
        }
        #pragma unroll
        for (int im = 0; im < 4; im++) {
            #pragma unroll
            for (int jn = 0; jn < 4; jn++) {
                mma16816(c[im][jn], a[im], b[jn >> 1][jn & 1], b[jn >> 1][2 + (jn & 1)]);
            }
        }
    }
}

// 3-stage cp.async pipeline over K tiles of 64. A:[M,K] row-major, B:[N,K] row-major.
__device__ __forceinline__ void gemm_loop(const __half* __restrict__ Ag, int lda,
                                          const __half* __restrict__ Bg, int ldb,
                                          int m0, int n0, int ktiles,
                                          uint32_t s, float (&c)[4][4][4]) {
    const int tid = threadIdx.x;
    const int lane = tid & 31;
    const int wid = tid >> 5;
    const int wm = wid >> 2;
    const int wn = wid & 3;

    load_tile(s, Ag, lda, m0, 0, tid);
    load_tile(s + 16384, Bg, ldb, n0, 0, tid);
    cp_commit();
    load_tile(s + 32768, Ag, lda, m0, 64, tid);
    load_tile(s + 32768 + 16384, Bg, ldb, n0, 64, tid);
    cp_commit();

    for (int kt = 0; kt < ktiles; kt++) {
        int st = kt % 3;
        if (kt + 2 < ktiles) {
            int st2 = (kt + 2) % 3;
            load_tile(s + st2 * 32768, Ag, lda, m0, (kt + 2) * 64, tid);
            load_tile(s + st2 * 32768 + 16384, Bg, ldb, n0, (kt + 2) * 64, tid);
            cp_commit();
            cp_wait<2>();
        } else {
            cp_wait<0>();
        }
        __syncthreads();
        mma_stage(s + st * 32768, s + st * 32768 + 16384, lane, wm, wn, c);
        __syncthreads();
    }
}

// ---------------- GEMM 1: xr[8192,256] = xh @ rh^T (fp16 out) ----------------
__global__ void gemm_xr_kernel() {
    extern __shared__ char smem[];
    uint32_t s = (uint32_t)__cvta_generic_to_shared(smem);
    float c[4][4][4];
    #pragma unroll
    for (int i = 0; i < 4; i++)
        #pragma unroll
        for (int j = 0; j < 4; j++)
            #pragma unroll
            for (int k = 0; k < 4; k++) c[i][j][k] = 0.f;

    const int m0 = blockIdx.x * 128;
    const int n0 = blockIdx.y * 128;
    gemm_loop(g_xh, DIN, g_rh, DIN, m0, n0, DIN / 64, s, c);

    const int lane = threadIdx.x & 31;
    const int wid = threadIdx.x >> 5;
    const int wm = wid >> 2, wn = wid & 3;
    #pragma unroll
    for (int im = 0; im < 4; im++) {
        #pragma unroll
        for (int jn = 0; jn < 4; jn++) {
            int row = m0 + wm * 64 + im * 16 + (lane >> 2);
            int col = n0 + wn * 32 + jn * 8 + (lane & 3) * 2;
            __half2 v0 = __floats2half2_rn(c[im][jn][0], c[im][jn][1]);
            __half2 v1 = __floats2half2_rn(c[im][jn][2], c[im][jn][3]);
            *reinterpret_cast<__half2*>(&g_xr[(size_t)row * RANK + col]) = v0;
            *reinterpret_cast<__half2*>(&g_xr[(size_t)(row + 8) * RANK + col]) = v1;
        }
    }
}

// ------- GEMM 2 (fused): out = xh @ qh^T + xr @ lh^T + bias (fp32 out) -------
__global__ void gemm_main_kernel(const float* __restrict__ bias, float* __restrict__ out) {
    extern __shared__ char smem[];
    uint32_t s = (uint32_t)__cvta_generic_to_shared(smem);
    float c[4][4][4];
    #pragma unroll
    for (int i = 0; i < 4; i++)
        #pragma unroll
        for (int j = 0; j < 4; j++)
            #pragma unroll
            for (int k = 0; k < 4; k++) c[i][j][k] = 0.f;

    const int m0 = blockIdx.x * 128;
    const int n0 = blockIdx.y * 128;
    gemm_loop(g_xh, DIN, g_qh, DIN, m0, n0, DIN / 64, s, c);   // K = 4096
    gemm_loop(g_xr, RANK, g_lh, RANK, m0, n0, RANK / 64, s, c); // K = 256

    const int lane = threadIdx.x & 31;
    const int wid = threadIdx.x >> 5;
    const int wm = wid >> 2, wn = wid & 3;
    #pragma unroll
    for (int im = 0; im < 4; im++) {
        #pragma unroll
        for (int jn = 0; jn < 4; jn++) {
            int row = m0 + wm * 64 + im * 16 + (lane >> 2);
            int col = n0 + wn * 32 + jn * 8 + (lane & 3) * 2;
            float b0 = bias[col];
            float b1 = bias[col + 1];
            float2 v0 = make_float2(c[im][jn][0] + b0, c[im][jn][1] + b1);
            float2 v1 = make_float2(c[im][jn][2] + b0, c[im][jn][3] + b1);
            *reinterpret_cast<float2*>(out + (size_t)row * DOUT + col) = v0;
            *reinterpret_cast<float2*>(out + (size_t)(row + 8) * DOUT + col) = v1;
        }
    }
}

// ---------------- launch ----------------
extern "C" void kernel_launch(void* const* d_in, const int* in_sizes, int n_in,
                              void* d_out, int out_size) {
    const float* x    = (const float*)d_in[0];
    const int*   qv   = (const int*)  d_in[1];
    const float* qs   = (const float*)d_in[2];
    const int*   lv   = (const int*)  d_in[3];
    const float* ls   = (const float*)d_in[4];
    const int*   rv   = (const int*)  d_in[5];
    const float* rs   = (const float*)d_in[6];
    const float* bias = (const float*)d_in[7];
    float* out = (float*)d_out;

    __half *pq, *pr, *pl;
    cudaGetSymbolAddress((void**)&pq, g_qh);
    cudaGetSymbolAddress((void**)&pr, g_rh);
    cudaGetSymbolAddress((void**)&pl, g_lh);

    const int SMEM = 3 * 32768;  // 96 KB dynamic
    cudaFuncSetAttribute(gemm_xr_kernel, cudaFuncAttributeMaxDynamicSharedMemorySize, SMEM);
    cudaFuncSetAttribute(gemm_main_kernel, cudaFuncAttributeMaxDynamicSharedMemorySize, SMEM);

    cvt_x_kernel<<<(TOKENS * DIN / 4) / 256, 256>>>(x);
    deq_kernel<<<((size_t)DOUT * DIN / 4) / 256, 256>>>(qv, qs, pq, 12);  // cols=4096
    deq_kernel<<<((size_t)RANK * DIN / 4) / 256, 256>>>(rv, rs, pr, 12);  // cols=4096
    deq_kernel<<<((size_t)DOUT * RANK / 4) / 256, 256>>>(lv, ls, pl, 8);  // cols=256

    gemm_xr_kernel<<<dim3(TOKENS / 128, RANK / 128), 256, SMEM>>>();
    gemm_main_kernel<<<dim3(TOKENS / 128, DOUT / 128), 256, SMEM>>>(bias, out);
}